// round 13
// baseline (speedup 1.0000x reference)
#include <cuda_runtime.h>
#include <cuda_bf16.h>
#include <cuda_fp8.h>
#include <cstdint>

// Problem shape (fixed by the dataset)
#define M_TOT 32768
#define K_TOT 1024
#define N_TOT 1024
#define NB    8      // number of 128-wide K blocks
#define BSQ   128

// ---------------- scratch (static __device__, no allocations) ----------------
__device__ uint8_t g_xq [(size_t)M_TOT * K_TOT];   // e4m3 quantized x
__device__ uint8_t g_whi[(size_t)N_TOT * K_TOT];   // e4m3 weight hi
__device__ uint8_t g_wlo[(size_t)N_TOT * K_TOT];   // e4m3 weight lo (residual)
__device__ float   g_dx [(size_t)NB * M_TOT];      // [b][m] dequant factor 1/scale
__device__ float   g_dhi[(size_t)NB * N_TOT];      // [b][n]
__device__ float   g_dlo[(size_t)NB * N_TOT];      // [b][n]

// ---------------- PTX helpers ----------------
__device__ __forceinline__ uint32_t smem_u32(const void* p) {
    uint32_t a;
    asm("{ .reg .u64 t; cvta.to.shared.u64 t, %1; cvt.u32.u64 %0, t; }" : "=r"(a) : "l"(p));
    return a;
}
#define CP_ASYNC16(saddr, gptr) \
    asm volatile("cp.async.cg.shared.global [%0], [%1], 16;" :: "r"(saddr), "l"(gptr) : "memory")

#define MBAR_INIT(addr, cnt) \
    asm volatile("mbarrier.init.shared.b64 [%0], %1;" :: "r"(addr), "r"(cnt) : "memory")
// .noinc: the init count already accounts for this async arrival
#define CP_MBAR_ARRIVE_NOINC(addr) \
    asm volatile("cp.async.mbarrier.arrive.noinc.shared::cta.b64 [%0];" :: "r"(addr) : "memory")
#define MBAR_ARRIVE(addr) \
    asm volatile("mbarrier.arrive.shared::cta.b64 _, [%0];" :: "r"(addr) : "memory")

#define MBARRIER_WAIT_PARITY(addr, par) do { \
    uint32_t _m = (addr), _p = (par), _d; \
    asm volatile("{\n\t.reg .pred p;\n\t" \
        "mbarrier.try_wait.parity.acquire.cta.shared::cta.b64 p, [%1], %2;\n\t" \
        "selp.b32 %0, 1, 0, p;\n\t}" : "=r"(_d) : "r"(_m), "r"(_p) : "memory"); \
    if (!_d) { \
        asm volatile("{\n\t.reg .pred P1;\n\t" \
            "WL_%=:\n\t" \
            "mbarrier.try_wait.parity.acquire.cta.shared::cta.b64 P1, [%0], %1, 0x989680;\n\t" \
            "@P1 bra.uni WD_%=;\n\t" \
            "bra.uni WL_%=;\n\t" \
            "WD_%=:\n\t}" :: "r"(_m), "r"(_p) : "memory"); \
    } \
} while (0)

// ldmatrix x4: four 8x8 b16 matrices -> 4 regs/lane
__device__ __forceinline__ void ldsm4(uint32_t* r, uint32_t addr) {
    asm volatile("ldmatrix.sync.aligned.m8n8.x4.shared.b16 {%0,%1,%2,%3}, [%4];"
        : "=r"(r[0]), "=r"(r[1]), "=r"(r[2]), "=r"(r[3]) : "r"(addr));
}

// fp8 e4m3 MMA accumulate: D += A*B (D==C)
__device__ __forceinline__ void mma_e4m3(float* c, const uint32_t* a,
                                         uint32_t b0, uint32_t b1) {
    asm volatile(
        "mma.sync.aligned.m16n8k32.row.col.f32.e4m3.e4m3.f32 "
        "{%0,%1,%2,%3}, {%4,%5,%6,%7}, {%8,%9}, {%0,%1,%2,%3};"
        : "+f"(c[0]), "+f"(c[1]), "+f"(c[2]), "+f"(c[3])
        : "r"(a[0]), "r"(a[1]), "r"(a[2]), "r"(a[3]), "r"(b0), "r"(b1));
}
// fp8 e4m3 MMA init: D = A*B + 0 (no P zeroing needed)
__device__ __forceinline__ void mma_e4m3_z(float* d, const uint32_t* a,
                                           uint32_t b0, uint32_t b1) {
    asm volatile(
        "mma.sync.aligned.m16n8k32.row.col.f32.e4m3.e4m3.f32 "
        "{%0,%1,%2,%3}, {%4,%5,%6,%7}, {%8,%9}, {%10,%10,%10,%10};"
        : "=f"(d[0]), "=f"(d[1]), "=f"(d[2]), "=f"(d[3])
        : "r"(a[0]), "r"(a[1]), "r"(a[2]), "r"(a[3]), "r"(b0), "r"(b1), "f"(0.0f));
}

// ---- packed f32x2 helpers ----
__device__ __forceinline__ uint64_t pack2(float lo, float hi) {
    uint64_t r;
    asm("mov.b64 %0, {%1, %2};" : "=l"(r) : "f"(lo), "f"(hi));
    return r;
}
__device__ __forceinline__ uint64_t mul2(uint64_t a, uint64_t b) {
    uint64_t r;
    asm("mul.rn.f32x2 %0, %1, %2;" : "=l"(r) : "l"(a), "l"(b));
    return r;
}
__device__ __forceinline__ void fma2(uint64_t& c, uint64_t a, uint64_t b) {
    asm("fma.rn.f32x2 %0, %1, %2, %0;" : "+l"(c) : "l"(a), "l"(b));
}
__device__ __forceinline__ float2 unpack2(uint64_t v) {
    float2 f;
    asm("mov.b64 {%0, %1}, %2;" : "=f"(f.x), "=f"(f.y) : "l"(v));
    return f;
}

// ---------------- quant helpers ----------------
__device__ __forceinline__ float warp_max(float v) {
#pragma unroll
    for (int o = 16; o > 0; o >>= 1)
        v = fmaxf(v, __shfl_xor_sync(0xffffffffu, v, o));
    return v;
}
__device__ __forceinline__ uint8_t quant_e4m3(float x, float scale) {
    float q = fminf(fmaxf(x * scale, -448.0f), 448.0f);
    return (uint8_t)__nv_cvt_float_to_fp8(q, __NV_SATFINITE, __NV_E4M3);
}
__device__ __forceinline__ float deq_e4m3(uint8_t s, float scale) {
    return __half2float(__nv_cvt_fp8_to_halfraw((__nv_fp8_storage_t)s, __NV_E4M3)) / scale;
}
__device__ __forceinline__ uint32_t cvt4_e4m3(float f0, float f1, float f2, float f3) {
    uint16_t lo, hi;
    asm("cvt.rn.satfinite.e4m3x2.f32 %0, %1, %2;" : "=h"(lo) : "f"(f1), "f"(f0));
    asm("cvt.rn.satfinite.e4m3x2.f32 %0, %1, %2;" : "=h"(hi) : "f"(f3), "f"(f2));
    return (uint32_t)lo | ((uint32_t)hi << 16);
}

// ---------------- fused quant kernel (round-12, proven) ----------------
#define XBLOCKS 4096
__global__ void __launch_bounds__(256) quant_fused_kernel(const float* __restrict__ x,
                                                          const float* __restrict__ w) {
    int lane = threadIdx.x & 31;

    if (blockIdx.x < XBLOCKS) {
        int row = (blockIdx.x * 256 + threadIdx.x) >> 5;
        const float4* px = (const float4*)(x + (size_t)row * K_TOT);
        float4 v[8];
#pragma unroll
        for (int k = 0; k < 8; k++) v[k] = px[lane + 32 * k];

        float a[8];
#pragma unroll
        for (int k = 0; k < 8; k++)
            a[k] = fmaxf(fmaxf(fabsf(v[k].x), fabsf(v[k].y)),
                         fmaxf(fabsf(v[k].z), fabsf(v[k].w)));
#pragma unroll
        for (int o = 16; o > 0; o >>= 1) {
#pragma unroll
            for (int k = 0; k < 8; k++)
                a[k] = fmaxf(a[k], __shfl_xor_sync(0xffffffffu, a[k], o));
        }

        float s[8], d[8];
#pragma unroll
        for (int k = 0; k < 8; k++) {
            float am = fmaxf(a[k], 1e-12f);
            s[k] = 448.0f / am;
            d[k] = 1.0f / s[k];
        }

        uint32_t* pq = (uint32_t*)(g_xq + (size_t)row * K_TOT);
#pragma unroll
        for (int k = 0; k < 8; k++)
            pq[lane + 32 * k] = cvt4_e4m3(v[k].x * s[k], v[k].y * s[k],
                                          v[k].z * s[k], v[k].w * s[k]);
        if (lane == 0) {
#pragma unroll
            for (int k = 0; k < 8; k++)
                g_dx[(size_t)k * M_TOT + row] = d[k];
        }
    } else {
        int wg = ((blockIdx.x - XBLOCKS) * 256 + threadIdx.x) >> 5;  // 0..8191
        int row = wg >> 3;
        int kb  = wg & 7;

        size_t base = (size_t)row * K_TOT + kb * BSQ;
        float4 v = ((const float4*)(w + base))[lane];
        float vv[4] = {v.x, v.y, v.z, v.w};

        float amax = fmaxf(fmaxf(fabsf(vv[0]), fabsf(vv[1])),
                           fmaxf(fabsf(vv[2]), fabsf(vv[3])));
        amax = fmaxf(warp_max(amax), 1e-12f);
        float s1 = 448.0f / amax;

        uint8_t qh[4];
        float r[4];
#pragma unroll
        for (int j = 0; j < 4; j++) {
            qh[j] = quant_e4m3(vv[j], s1);
            r[j]  = vv[j] - deq_e4m3(qh[j], s1);
        }

        float amax2 = fmaxf(fmaxf(fabsf(r[0]), fabsf(r[1])),
                            fmaxf(fabsf(r[2]), fabsf(r[3])));
        amax2 = fmaxf(warp_max(amax2), 1e-12f);
        float s2 = 448.0f / amax2;

        uint32_t ph = 0, pl = 0;
#pragma unroll
        for (int j = 0; j < 4; j++) {
            ph |= (uint32_t)qh[j] << (j * 8);
            pl |= (uint32_t)quant_e4m3(r[j], s2) << (j * 8);
        }
        size_t off = base + (size_t)lane * 4;
        *((uint32_t*)(g_whi + off)) = ph;
        *((uint32_t*)(g_wlo + off)) = pl;
        if (lane == 0) {
            g_dhi[(size_t)kb * N_TOT + row] = 1.0f / s1;
            g_dlo[(size_t)kb * N_TOT + row] = 1.0f / s2;
        }
    }
}

// ---------------- kernel 3: block-scaled FP8 GEMM ----------------
// CTA tile 128(M)x64(N), 256 threads (8 warps, 4x2 grid of 32x32 warp tiles).
// Iterates per 128-K quant BLOCK, consuming TWO 64-K stages per iteration;
// P accumulates across the full block per phase -> rescale once per phase
// (half the fma/alu rescale traffic vs per-step rescale).
// mbarrier producer-consumer pipeline, NSTAGE=6, SW64 swizzle, 2 CTAs/SM.
#define BM 128
#define BN 64
#define NSTEP 16                   // 64-wide stages
#define X_TILE 8192                // 128 rows x 64 B
#define W_TILE 4096                // 64 rows x 64 B
#define STAGE_B (X_TILE + 2 * W_TILE)   // 16384
#define NSTAGE 6
#define MBAR_OFF (NSTAGE * STAGE_B)          // 98304
#define SCALES_OFF (MBAR_OFF + 128)
#define SCALES_B (4 * (NB * BM + 2 * NB * BN))   // 8192
#define SMEM_BYTES (1024 + SCALES_OFF + SCALES_B)  // 107648

__global__ void __launch_bounds__(256, 2)
gemm_kernel(const float* __restrict__ bias, float* __restrict__ out) {
    extern __shared__ char smem_raw[];
    char* tile = smem_raw + ((1024 - ((uintptr_t)smem_raw & 1023)) & 1023);
    const uint32_t tile_u = smem_u32(tile);

    float* dx_s  = (float*)(tile + SCALES_OFF);   // [NB][BM]
    float* dhi_s = dx_s + NB * BM;                // [NB][BN]
    float* dlo_s = dhi_s + NB * BN;

    const int tid  = threadIdx.x;
    const int lane = tid & 31;
    const int wid  = tid >> 5;
    const int gid  = lane >> 2;
    const int tig  = lane & 3;
    const int wm   = (wid & 3) * 32;   // 0..96
    const int wn   = (wid >> 2) * 32;  // 0 or 32

    const int bn = blockIdx.x;   // 0..15
    const int bm = blockIdx.y;   // 0..255
    const size_t arow0 = (size_t)bm * BM;
    const size_t brow0 = (size_t)bn * BN;

    const uint32_t full0  = tile_u + MBAR_OFF;
    const uint32_t empty0 = tile_u + MBAR_OFF + 64;

    if (tid == 0) {
#pragma unroll
        for (int i = 0; i < NSTAGE; i++) {
            MBAR_INIT(full0 + i * 8, 256);
            MBAR_INIT(empty0 + i * 8, 8);
        }
    }

    // ---- ldmatrix per-lane constants (SW64: col ^= (row&6)<<3) ----
    const uint32_t arow_l = (uint32_t)(wm + ((lane >> 3) & 1) * 8 + (lane & 7));
    const uint32_t acb    = ((uint32_t)(lane >> 4) & 1) * 16;
    const uint32_t xa     = (arow_l & 6) << 3;
    const uint32_t brow_l = (uint32_t)(wn + ((lane >> 4) & 1) * 8 + (lane & 7));
    const uint32_t bcb    = ((uint32_t)(lane >> 3) & 1) * 16;
    const uint32_t xb     = (brow_l & 6) << 3;

    // ---- per-block scales into smem ----
    for (int i = tid; i < NB * BM; i += 256)
        dx_s[i] = __ldg(&g_dx[(size_t)(i >> 7) * M_TOT + arow0 + (i & 127)]);
    for (int i = tid; i < NB * BN; i += 256) {
        int b = i >> 6, r = i & 63;
        dhi_s[i] = __ldg(&g_dhi[(size_t)b * N_TOT + brow0 + r]);
        dlo_s[i] = __ldg(&g_dlo[(size_t)b * N_TOT + brow0 + r]);
    }
    __syncthreads();   // mbarrier init + scales visible

    // ---- stage loader (one 64-K stage) ----
    auto load_stage = [&](int st_idx, int s) {
        uint32_t st = tile_u + st_idx * STAGE_B;
        int koff = s * 64;
#pragma unroll
        for (int j = 0; j < 2; j++) {          // X: 512 chunks
            int idx = tid + j * 256;
            int r = idx >> 2, c = idx & 3;
            uint32_t so = r * 64 + ((c * 16) ^ ((r & 6) << 3));
            CP_ASYNC16(st + so, g_xq + (arow0 + r) * K_TOT + koff + c * 16);
        }
        {                                       // Whi + Wlo: 256 chunks each
            int r = tid >> 2, c = tid & 3;
            uint32_t so = r * 64 + ((c * 16) ^ ((r & 6) << 3));
            size_t go = (brow0 + r) * K_TOT + koff + c * 16;
            CP_ASYNC16(st + X_TILE + so, g_whi + go);
            CP_ASYNC16(st + X_TILE + W_TILE + so, g_wlo + go);
        }
    };

    // producer/consumer cursors (per-thread)
    int ps = 0, pw = 1, prodn = 0;
    int cs = 0, cp = 0;

    auto produce = [&](int kt) {
        if (prodn >= NSTAGE) MBARRIER_WAIT_PARITY(empty0 + ps * 8, (uint32_t)pw);
        load_stage(ps, kt);
        CP_MBAR_ARRIVE_NOINC(full0 + ps * 8);
        prodn++;
        if (++ps == NSTAGE) { ps = 0; pw ^= 1; }
    };

    // master accumulators as packed f32x2 pairs: [mi][ni][h]
    uint64_t acc2[2][4][2];
#pragma unroll
    for (int mi = 0; mi < 2; mi++)
#pragma unroll
        for (int ni = 0; ni < 4; ni++)
#pragma unroll
            for (int h = 0; h < 2; h++) acc2[mi][ni][h] = 0ull;

    // prologue: 4 stages (2 blocks) in flight
    produce(0);
    produce(1);
    produce(2);
    produce(3);

#pragma unroll 1
    for (int b = 0; b < NB; b++) {
        // refill next block's two stages
        if (2 * b + 4 < NSTEP) produce(2 * b + 4);
        if (2 * b + 5 < NSTEP) produce(2 * b + 5);

        // wait both stages of this quant block
        const int cs0 = cs, cp0 = cp;
        int cs1 = cs0 + 1, cp1 = cp0;
        if (cs1 == NSTAGE) { cs1 = 0; cp1 ^= 1; }
        MBARRIER_WAIT_PARITY(full0 + cs0 * 8, (uint32_t)cp0);
        MBARRIER_WAIT_PARITY(full0 + cs1 * 8, (uint32_t)cp1);
        const uint32_t Xu0 = tile_u + cs0 * STAGE_B;
        const uint32_t Xu1 = tile_u + cs1 * STAGE_B;

        // packed row scales (one load per block)
        uint64_t rsp[2][2];
#pragma unroll
        for (int mi = 0; mi < 2; mi++) {
            float r0 = dx_s[b * BM + wm + mi * 16 + gid];
            float r1 = dx_s[b * BM + wm + mi * 16 + gid + 8];
            rsp[mi][0] = pack2(r0, r0);
            rsp[mi][1] = pack2(r1, r1);
        }

#pragma unroll
        for (int ph = 0; ph < 2; ph++) {
            const float* dws = ph ? dlo_s : dhi_s;
            float P[2][4][4];

#pragma unroll
            for (int st = 0; st < 2; st++) {
                const uint32_t Xu = st ? Xu1 : Xu0;
                const uint32_t Wu = Xu + X_TILE + ph * W_TILE;
#pragma unroll
                for (int ks = 0; ks < 2; ks++) {
                    uint32_t ca = (acb + ks * 32) ^ xa;
                    uint32_t cb = (bcb + ks * 32) ^ xb;
                    uint32_t A0[4], A1[4], B0[4], B1[4];
                    ldsm4(A0, Xu + arow_l * 64 + ca);
                    ldsm4(A1, Xu + (arow_l + 16) * 64 + ca);
                    ldsm4(B0, Wu + brow_l * 64 + cb);
                    ldsm4(B1, Wu + (brow_l + 16) * 64 + cb);

                    if (st == 0 && ks == 0) {
                        mma_e4m3_z(P[0][0], A0, B0[0], B0[1]);
                        mma_e4m3_z(P[1][0], A1, B0[0], B0[1]);
                        mma_e4m3_z(P[0][1], A0, B0[2], B0[3]);
                        mma_e4m3_z(P[1][1], A1, B0[2], B0[3]);
                        mma_e4m3_z(P[0][2], A0, B1[0], B1[1]);
                        mma_e4m3_z(P[1][2], A1, B1[0], B1[1]);
                        mma_e4m3_z(P[0][3], A0, B1[2], B1[3]);
                        mma_e4m3_z(P[1][3], A1, B1[2], B1[3]);
                    } else {
                        mma_e4m3(P[0][0], A0, B0[0], B0[1]);
                        mma_e4m3(P[1][0], A1, B0[0], B0[1]);
                        mma_e4m3(P[0][1], A0, B0[2], B0[3]);
                        mma_e4m3(P[1][1], A1, B0[2], B0[3]);
                        mma_e4m3(P[0][2], A0, B1[0], B1[1]);
                        mma_e4m3(P[1][2], A1, B1[0], B1[1]);
                        mma_e4m3(P[0][3], A0, B1[2], B1[3]);
                        mma_e4m3(P[1][3], A1, B1[2], B1[3]);
                    }
                }
            }

            // rescale ONCE per phase per 128-K block
#pragma unroll
            for (int ni = 0; ni < 4; ni++) {
                const float2 cs2 = *(const float2*)(dws + b * BN + wn + ni * 8 + tig * 2);
                const uint64_t csp = pack2(cs2.x, cs2.y);
#pragma unroll
                for (int mi = 0; mi < 2; mi++) {
                    fma2(acc2[mi][ni][0], pack2(P[mi][ni][0], P[mi][ni][1]),
                         mul2(rsp[mi][0], csp));
                    fma2(acc2[mi][ni][1], pack2(P[mi][ni][2], P[mi][ni][3]),
                         mul2(rsp[mi][1], csp));
                }
            }
        }

        // release both stages
        __syncwarp();
        if (lane == 0) {
            MBAR_ARRIVE(empty0 + cs0 * 8);
            MBAR_ARRIVE(empty0 + cs1 * 8);
        }
        cs = cs1 + 1; cp = cp1;
        if (cs == NSTAGE) { cs = 0; cp ^= 1; }
    }

    // ---- epilogue: add bias, store float2 ----
#pragma unroll
    for (int mi = 0; mi < 2; mi++) {
#pragma unroll
        for (int h = 0; h < 2; h++) {
            size_t row = arow0 + wm + mi * 16 + gid + h * 8;
#pragma unroll
            for (int ni = 0; ni < 4; ni++) {
                int col = bn * BN + wn + ni * 8 + tig * 2;
                float2 bz = *(const float2*)(bias + col);
                float2 a = unpack2(acc2[mi][ni][h]);
                float2 v;
                v.x = a.x + bz.x;
                v.y = a.y + bz.y;
                *(float2*)(out + row * N_TOT + col) = v;
            }
        }
    }
}

// ---------------- launch ----------------
extern "C" void kernel_launch(void* const* d_in, const int* in_sizes, int n_in,
                              void* d_out, int out_size) {
    const float* x      = (const float*)d_in[0];
    const float* weight = (const float*)d_in[1];
    const float* bias   = (const float*)d_in[2];
    float* out          = (float*)d_out;

    // fused quantization: 4096 X-blocks + 128 W-blocks
    quant_fused_kernel<<<XBLOCKS + (N_TOT * NB) / 8, 256>>>(x, weight);

    static bool attr_set = false;
    if (!attr_set) {
        cudaFuncSetAttribute(gemm_kernel, cudaFuncAttributeMaxDynamicSharedMemorySize, SMEM_BYTES);
        attr_set = true;
    }
    dim3 grid(N_TOT / BN, M_TOT / BM);   // (16, 256)
    gemm_kernel<<<grid, 256, SMEM_BYTES>>>(bias, out);
}

// round 14
// speedup vs baseline: 1.2935x; 1.2935x over previous
#include <cuda_runtime.h>
#include <cuda_bf16.h>
#include <cuda_fp8.h>
#include <cstdint>

// Problem shape (fixed by the dataset)
#define M_TOT 32768
#define K_TOT 1024
#define N_TOT 1024
#define NB    8      // number of 128-wide K blocks
#define BSQ   128

// ---------------- scratch (static __device__, no allocations) ----------------
__device__ uint8_t g_xq [(size_t)M_TOT * K_TOT];   // e4m3 quantized x
__device__ uint8_t g_whi[(size_t)N_TOT * K_TOT];   // e4m3 weight hi
__device__ uint8_t g_wlo[(size_t)N_TOT * K_TOT];   // e4m3 weight lo (residual)
__device__ float   g_dx [(size_t)NB * M_TOT];      // [b][m] dequant factor 1/scale
__device__ float   g_dhi[(size_t)NB * N_TOT];      // [b][n]
__device__ float   g_dlo[(size_t)NB * N_TOT];      // [b][n]

// ---------------- PTX helpers ----------------
__device__ __forceinline__ uint32_t smem_u32(const void* p) {
    uint32_t a;
    asm("{ .reg .u64 t; cvta.to.shared.u64 t, %1; cvt.u32.u64 %0, t; }" : "=r"(a) : "l"(p));
    return a;
}
#define CP_ASYNC16(saddr, gptr) \
    asm volatile("cp.async.cg.shared.global [%0], [%1], 16;" :: "r"(saddr), "l"(gptr) : "memory")

#define MBAR_INIT(addr, cnt) \
    asm volatile("mbarrier.init.shared.b64 [%0], %1;" :: "r"(addr), "r"(cnt) : "memory")
// .noinc: the init count already accounts for this async arrival
#define CP_MBAR_ARRIVE_NOINC(addr) \
    asm volatile("cp.async.mbarrier.arrive.noinc.shared::cta.b64 [%0];" :: "r"(addr) : "memory")
#define MBAR_ARRIVE(addr) \
    asm volatile("mbarrier.arrive.shared::cta.b64 _, [%0];" :: "r"(addr) : "memory")

#define MBARRIER_WAIT_PARITY(addr, par) do { \
    uint32_t _m = (addr), _p = (par), _d; \
    asm volatile("{\n\t.reg .pred p;\n\t" \
        "mbarrier.try_wait.parity.acquire.cta.shared::cta.b64 p, [%1], %2;\n\t" \
        "selp.b32 %0, 1, 0, p;\n\t}" : "=r"(_d) : "r"(_m), "r"(_p) : "memory"); \
    if (!_d) { \
        asm volatile("{\n\t.reg .pred P1;\n\t" \
            "WL_%=:\n\t" \
            "mbarrier.try_wait.parity.acquire.cta.shared::cta.b64 P1, [%0], %1, 0x989680;\n\t" \
            "@P1 bra.uni WD_%=;\n\t" \
            "bra.uni WL_%=;\n\t" \
            "WD_%=:\n\t}" :: "r"(_m), "r"(_p) : "memory"); \
    } \
} while (0)

// ldmatrix x4: four 8x8 b16 matrices -> 4 regs/lane
__device__ __forceinline__ void ldsm4(uint32_t* r, uint32_t addr) {
    asm volatile("ldmatrix.sync.aligned.m8n8.x4.shared.b16 {%0,%1,%2,%3}, [%4];"
        : "=r"(r[0]), "=r"(r[1]), "=r"(r[2]), "=r"(r[3]) : "r"(addr));
}

// fp8 e4m3 MMA accumulate: D += A*B (D==C)
__device__ __forceinline__ void mma_e4m3(float* c, const uint32_t* a,
                                         uint32_t b0, uint32_t b1) {
    asm volatile(
        "mma.sync.aligned.m16n8k32.row.col.f32.e4m3.e4m3.f32 "
        "{%0,%1,%2,%3}, {%4,%5,%6,%7}, {%8,%9}, {%0,%1,%2,%3};"
        : "+f"(c[0]), "+f"(c[1]), "+f"(c[2]), "+f"(c[3])
        : "r"(a[0]), "r"(a[1]), "r"(a[2]), "r"(a[3]), "r"(b0), "r"(b1));
}
// fp8 e4m3 MMA init: D = A*B + 0 (no P zeroing needed)
__device__ __forceinline__ void mma_e4m3_z(float* d, const uint32_t* a,
                                           uint32_t b0, uint32_t b1) {
    asm volatile(
        "mma.sync.aligned.m16n8k32.row.col.f32.e4m3.e4m3.f32 "
        "{%0,%1,%2,%3}, {%4,%5,%6,%7}, {%8,%9}, {%10,%10,%10,%10};"
        : "=f"(d[0]), "=f"(d[1]), "=f"(d[2]), "=f"(d[3])
        : "r"(a[0]), "r"(a[1]), "r"(a[2]), "r"(a[3]), "r"(b0), "r"(b1), "f"(0.0f));
}

// ---- packed f32x2 helpers ----
__device__ __forceinline__ uint64_t pack2(float lo, float hi) {
    uint64_t r;
    asm("mov.b64 %0, {%1, %2};" : "=l"(r) : "f"(lo), "f"(hi));
    return r;
}
__device__ __forceinline__ uint64_t mul2(uint64_t a, uint64_t b) {
    uint64_t r;
    asm("mul.rn.f32x2 %0, %1, %2;" : "=l"(r) : "l"(a), "l"(b));
    return r;
}
__device__ __forceinline__ void fma2(uint64_t& c, uint64_t a, uint64_t b) {
    asm("fma.rn.f32x2 %0, %1, %2, %0;" : "+l"(c) : "l"(a), "l"(b));
}
__device__ __forceinline__ float2 unpack2(uint64_t v) {
    float2 f;
    asm("mov.b64 {%0, %1}, %2;" : "=f"(f.x), "=f"(f.y) : "l"(v));
    return f;
}

// ---------------- quant helpers ----------------
__device__ __forceinline__ float warp_max(float v) {
#pragma unroll
    for (int o = 16; o > 0; o >>= 1)
        v = fmaxf(v, __shfl_xor_sync(0xffffffffu, v, o));
    return v;
}
__device__ __forceinline__ uint8_t quant_e4m3(float x, float scale) {
    float q = fminf(fmaxf(x * scale, -448.0f), 448.0f);
    return (uint8_t)__nv_cvt_float_to_fp8(q, __NV_SATFINITE, __NV_E4M3);
}
__device__ __forceinline__ float deq_e4m3(uint8_t s, float scale) {
    return __half2float(__nv_cvt_fp8_to_halfraw((__nv_fp8_storage_t)s, __NV_E4M3)) / scale;
}
__device__ __forceinline__ uint32_t cvt4_e4m3(float f0, float f1, float f2, float f3) {
    uint16_t lo, hi;
    asm("cvt.rn.satfinite.e4m3x2.f32 %0, %1, %2;" : "=h"(lo) : "f"(f1), "f"(f0));
    asm("cvt.rn.satfinite.e4m3x2.f32 %0, %1, %2;" : "=h"(hi) : "f"(f3), "f"(f2));
    return (uint32_t)lo | ((uint32_t)hi << 16);
}

// ---------------- fused quant kernel (round-12, proven) ----------------
#define XBLOCKS 4096
__global__ void __launch_bounds__(256) quant_fused_kernel(const float* __restrict__ x,
                                                          const float* __restrict__ w) {
    int lane = threadIdx.x & 31;

    if (blockIdx.x < XBLOCKS) {
        int row = (blockIdx.x * 256 + threadIdx.x) >> 5;
        const float4* px = (const float4*)(x + (size_t)row * K_TOT);
        float4 v[8];
#pragma unroll
        for (int k = 0; k < 8; k++) v[k] = px[lane + 32 * k];

        float a[8];
#pragma unroll
        for (int k = 0; k < 8; k++)
            a[k] = fmaxf(fmaxf(fabsf(v[k].x), fabsf(v[k].y)),
                         fmaxf(fabsf(v[k].z), fabsf(v[k].w)));
#pragma unroll
        for (int o = 16; o > 0; o >>= 1) {
#pragma unroll
            for (int k = 0; k < 8; k++)
                a[k] = fmaxf(a[k], __shfl_xor_sync(0xffffffffu, a[k], o));
        }

        float s[8], d[8];
#pragma unroll
        for (int k = 0; k < 8; k++) {
            float am = fmaxf(a[k], 1e-12f);
            s[k] = 448.0f / am;
            d[k] = 1.0f / s[k];
        }

        uint32_t* pq = (uint32_t*)(g_xq + (size_t)row * K_TOT);
#pragma unroll
        for (int k = 0; k < 8; k++)
            pq[lane + 32 * k] = cvt4_e4m3(v[k].x * s[k], v[k].y * s[k],
                                          v[k].z * s[k], v[k].w * s[k]);
        if (lane == 0) {
#pragma unroll
            for (int k = 0; k < 8; k++)
                g_dx[(size_t)k * M_TOT + row] = d[k];
        }
    } else {
        int wg = ((blockIdx.x - XBLOCKS) * 256 + threadIdx.x) >> 5;  // 0..8191
        int row = wg >> 3;
        int kb  = wg & 7;

        size_t base = (size_t)row * K_TOT + kb * BSQ;
        float4 v = ((const float4*)(w + base))[lane];
        float vv[4] = {v.x, v.y, v.z, v.w};

        float amax = fmaxf(fmaxf(fabsf(vv[0]), fabsf(vv[1])),
                           fmaxf(fabsf(vv[2]), fabsf(vv[3])));
        amax = fmaxf(warp_max(amax), 1e-12f);
        float s1 = 448.0f / amax;

        uint8_t qh[4];
        float r[4];
#pragma unroll
        for (int j = 0; j < 4; j++) {
            qh[j] = quant_e4m3(vv[j], s1);
            r[j]  = vv[j] - deq_e4m3(qh[j], s1);
        }

        float amax2 = fmaxf(fmaxf(fabsf(r[0]), fabsf(r[1])),
                            fmaxf(fabsf(r[2]), fabsf(r[3])));
        amax2 = fmaxf(warp_max(amax2), 1e-12f);
        float s2 = 448.0f / amax2;

        uint32_t ph = 0, pl = 0;
#pragma unroll
        for (int j = 0; j < 4; j++) {
            ph |= (uint32_t)qh[j] << (j * 8);
            pl |= (uint32_t)quant_e4m3(r[j], s2) << (j * 8);
        }
        size_t off = base + (size_t)lane * 4;
        *((uint32_t*)(g_whi + off)) = ph;
        *((uint32_t*)(g_wlo + off)) = pl;
        if (lane == 0) {
            g_dhi[(size_t)kb * N_TOT + row] = 1.0f / s1;
            g_dlo[(size_t)kb * N_TOT + row] = 1.0f / s2;
        }
    }
}

// ---------------- kernel 3: block-scaled FP8 GEMM (round-12 best, hoisted addr) ----------------
// CTA tile 128(M)x64(N), 256 threads (8 warps, 4x2 grid of 32x32 warp tiles).
// K stepped in 64-wide halves (16 steps), SW64 swizzle, 2 CTAs/SM.
// mbarrier producer-consumer pipeline (NSTAGE=5, produce-distance 3).
// Producer addresses fully hoisted: 4 cp.async + 1 add per produce.
#define BM 128
#define BN 64
#define NSTEP 16                   // K steps of 64
#define X_TILE 8192                // 128 rows x 64 B
#define W_TILE 4096                // 64 rows x 64 B
#define STAGE_B (X_TILE + 2 * W_TILE)   // 16384
#define NSTAGE 5
#define PROD_DIST 3
#define MBAR_OFF (NSTAGE * STAGE_B)          // 81920
#define SCALES_OFF (MBAR_OFF + 128)
#define SCALES_B (4 * (NB * BM + 2 * NB * BN))   // 8192
#define SMEM_BYTES (1024 + SCALES_OFF + SCALES_B)  // 91264

__global__ void __launch_bounds__(256, 2)
gemm_kernel(const float* __restrict__ bias, float* __restrict__ out) {
    extern __shared__ char smem_raw[];
    char* tile = smem_raw + ((1024 - ((uintptr_t)smem_raw & 1023)) & 1023);
    const uint32_t tile_u = smem_u32(tile);

    float* dx_s  = (float*)(tile + SCALES_OFF);   // [NB][BM]
    float* dhi_s = dx_s + NB * BM;                // [NB][BN]
    float* dlo_s = dhi_s + NB * BN;

    const int tid  = threadIdx.x;
    const int lane = tid & 31;
    const int wid  = tid >> 5;
    const int gid  = lane >> 2;
    const int tig  = lane & 3;
    const int wm   = (wid & 3) * 32;   // 0..96
    const int wn   = (wid >> 2) * 32;  // 0 or 32

    const int bn = blockIdx.x;   // 0..15
    const int bm = blockIdx.y;   // 0..255
    const size_t arow0 = (size_t)bm * BM;
    const size_t brow0 = (size_t)bn * BN;

    // mbarriers: full[i] at MBAR_OFF + 8i, empty[i] at MBAR_OFF + 64 + 8i
    const uint32_t full0  = tile_u + MBAR_OFF;
    const uint32_t empty0 = tile_u + MBAR_OFF + 64;

    if (tid == 0) {
#pragma unroll
        for (int i = 0; i < NSTAGE; i++) {
            MBAR_INIT(full0 + i * 8, 256);   // 256 noinc async arrivals per production
            MBAR_INIT(empty0 + i * 8, 8);    // one arrive per warp per consumption
        }
    }

    // ---- ldmatrix per-lane constants (SW64: col ^= (row&6)<<3) ----
    const uint32_t arow_l = (uint32_t)(wm + ((lane >> 3) & 1) * 8 + (lane & 7));
    const uint32_t acb    = ((uint32_t)(lane >> 4) & 1) * 16;
    const uint32_t xa     = (arow_l & 6) << 3;
    const uint32_t brow_l = (uint32_t)(wn + ((lane >> 4) & 1) * 8 + (lane & 7));
    const uint32_t bcb    = ((uint32_t)(lane >> 3) & 1) * 16;
    const uint32_t xb     = (brow_l & 6) << 3;

    // ---- hoisted producer addressing (loop-invariant) ----
    const int xr0 = tid >> 2, xc0 = tid & 3;                 // X chunk 0 / W chunk
    const int xr1 = (tid + 256) >> 2, xc1 = (tid + 256) & 3; // X chunk 1
    const uint32_t so0 = (uint32_t)(xr0 * 64 + ((xc0 * 16) ^ ((xr0 & 6) << 3)));
    const uint32_t so1 = (uint32_t)(xr1 * 64 + ((xc1 * 16) ^ ((xr1 & 6) << 3)));
    const uint8_t* gx0 = g_xq  + (arow0 + xr0) * K_TOT + xc0 * 16;
    const uint8_t* gx1 = g_xq  + (arow0 + xr1) * K_TOT + xc1 * 16;
    const uint8_t* gwh = g_whi + (brow0 + xr0) * K_TOT + xc0 * 16;
    const uint8_t* gwl = g_wlo + (brow0 + xr0) * K_TOT + xc0 * 16;

    // ---- per-block scales into smem ----
    for (int i = tid; i < NB * BM; i += 256)
        dx_s[i] = __ldg(&g_dx[(size_t)(i >> 7) * M_TOT + arow0 + (i & 127)]);
    for (int i = tid; i < NB * BN; i += 256) {
        int b = i >> 6, r = i & 63;
        dhi_s[i] = __ldg(&g_dhi[(size_t)b * N_TOT + brow0 + r]);
        dlo_s[i] = __ldg(&g_dlo[(size_t)b * N_TOT + brow0 + r]);
    }
    __syncthreads();   // mbarrier init + scales visible

    // ---- stage loader: 4 cp.async, all addressing hoisted ----
    auto load_stage = [&](int st_idx, int s) {
        const uint32_t st = tile_u + st_idx * STAGE_B;
        const int koff = s * 64;
        CP_ASYNC16(st + so0, gx0 + koff);
        CP_ASYNC16(st + so1, gx1 + koff);
        CP_ASYNC16(st + X_TILE + so0, gwh + koff);
        CP_ASYNC16(st + X_TILE + W_TILE + so0, gwl + koff);
    };

    // producer/consumer cursors (per-thread)
    int ps = 0, pw = 1, prodn = 0;
    int cs = 0, cp = 0;

    auto produce = [&](int kt) {
        if (prodn >= NSTAGE) MBARRIER_WAIT_PARITY(empty0 + ps * 8, (uint32_t)pw);
        load_stage(ps, kt);
        CP_MBAR_ARRIVE_NOINC(full0 + ps * 8);
        prodn++;
        if (++ps == NSTAGE) { ps = 0; pw ^= 1; }
    };

    // master accumulators as packed f32x2 pairs: [mi][ni][h]
    uint64_t acc2[2][4][2];
#pragma unroll
    for (int mi = 0; mi < 2; mi++)
#pragma unroll
        for (int ni = 0; ni < 4; ni++)
#pragma unroll
            for (int h = 0; h < 2; h++) acc2[mi][ni][h] = 0ull;

    // prologue: produce PROD_DIST stages
    produce(0);
    produce(1);
    produce(2);

#pragma unroll 1
    for (int s = 0; s < NSTEP; s++) {
        if (s + PROD_DIST < NSTEP) produce(s + PROD_DIST);

        // wait this step's stage
        MBARRIER_WAIT_PARITY(full0 + cs * 8, (uint32_t)cp);
        const uint32_t Xu = tile_u + cs * STAGE_B;
        const int b = s >> 1;

        // A fragments for both k-halves (shared across hi/lo phases)
        uint32_t A[2][2][4];
#pragma unroll
        for (int ks = 0; ks < 2; ks++) {
            uint32_t ca = (acb + ks * 32) ^ xa;
            ldsm4(A[0][ks], Xu + arow_l * 64 + ca);
            ldsm4(A[1][ks], Xu + (arow_l + 16) * 64 + ca);
        }

        // packed row scales, shared by both phases
        uint64_t rsp[2][2];
#pragma unroll
        for (int mi = 0; mi < 2; mi++) {
            float r0 = dx_s[b * BM + wm + mi * 16 + gid];
            float r1 = dx_s[b * BM + wm + mi * 16 + gid + 8];
            rsp[mi][0] = pack2(r0, r0);
            rsp[mi][1] = pack2(r1, r1);
        }

#pragma unroll
        for (int ph = 0; ph < 2; ph++) {
            const uint32_t Wu = Xu + X_TILE + ph * W_TILE;
            const float* dws = ph ? dlo_s : dhi_s;

            float P[2][4][4];

#pragma unroll
            for (int ks = 0; ks < 2; ks++) {
                uint32_t cb = (bcb + ks * 32) ^ xb;
                uint32_t B0[4], B1[4];
                ldsm4(B0, Wu + brow_l * 64 + cb);
                ldsm4(B1, Wu + (brow_l + 16) * 64 + cb);

                if (ks == 0) {
                    mma_e4m3_z(P[0][0], A[0][0], B0[0], B0[1]);
                    mma_e4m3_z(P[1][0], A[1][0], B0[0], B0[1]);
                    mma_e4m3_z(P[0][1], A[0][0], B0[2], B0[3]);
                    mma_e4m3_z(P[1][1], A[1][0], B0[2], B0[3]);
                    mma_e4m3_z(P[0][2], A[0][0], B1[0], B1[1]);
                    mma_e4m3_z(P[1][2], A[1][0], B1[0], B1[1]);
                    mma_e4m3_z(P[0][3], A[0][0], B1[2], B1[3]);
                    mma_e4m3_z(P[1][3], A[1][0], B1[2], B1[3]);
                } else {
                    mma_e4m3(P[0][0], A[0][1], B0[0], B0[1]);
                    mma_e4m3(P[1][0], A[1][1], B0[0], B0[1]);
                    mma_e4m3(P[0][1], A[0][1], B0[2], B0[3]);
                    mma_e4m3(P[1][1], A[1][1], B0[2], B0[3]);
                    mma_e4m3(P[0][2], A[0][1], B1[0], B1[1]);
                    mma_e4m3(P[1][2], A[1][1], B1[0], B1[1]);
                    mma_e4m3(P[0][3], A[0][1], B1[2], B1[3]);
                    mma_e4m3(P[1][3], A[1][1], B1[2], B1[3]);
                }
            }

            // packed rescale: acc2 += P_pair * (rs*cs)_pair
#pragma unroll
            for (int ni = 0; ni < 4; ni++) {
                const float2 cs2 = *(const float2*)(dws + b * BN + wn + ni * 8 + tig * 2);
                const uint64_t csp = pack2(cs2.x, cs2.y);
#pragma unroll
                for (int mi = 0; mi < 2; mi++) {
                    fma2(acc2[mi][ni][0], pack2(P[mi][ni][0], P[mi][ni][1]),
                         mul2(rsp[mi][0], csp));
                    fma2(acc2[mi][ni][1], pack2(P[mi][ni][2], P[mi][ni][3]),
                         mul2(rsp[mi][1], csp));
                }
            }
        }

        // release stage: one arrive per warp
        __syncwarp();
        if (lane == 0) MBAR_ARRIVE(empty0 + cs * 8);
        if (++cs == NSTAGE) { cs = 0; cp ^= 1; }
    }

    // ---- epilogue: add bias, store float2 ----
#pragma unroll
    for (int mi = 0; mi < 2; mi++) {
#pragma unroll
        for (int h = 0; h < 2; h++) {
            size_t row = arow0 + wm + mi * 16 + gid + h * 8;
#pragma unroll
            for (int ni = 0; ni < 4; ni++) {
                int col = bn * BN + wn + ni * 8 + tig * 2;
                float2 bz = *(const float2*)(bias + col);
                float2 a = unpack2(acc2[mi][ni][h]);
                float2 v;
                v.x = a.x + bz.x;
                v.y = a.y + bz.y;
                *(float2*)(out + row * N_TOT + col) = v;
            }
        }
    }
}

// ---------------- launch ----------------
extern "C" void kernel_launch(void* const* d_in, const int* in_sizes, int n_in,
                              void* d_out, int out_size) {
    const float* x      = (const float*)d_in[0];
    const float* weight = (const float*)d_in[1];
    const float* bias   = (const float*)d_in[2];
    float* out          = (float*)d_out;

    // fused quantization: 4096 X-blocks + 128 W-blocks
    quant_fused_kernel<<<XBLOCKS + (N_TOT * NB) / 8, 256>>>(x, weight);

    static bool attr_set = false;
    if (!attr_set) {
        cudaFuncSetAttribute(gemm_kernel, cudaFuncAttributeMaxDynamicSharedMemorySize, SMEM_BYTES);
        attr_set = true;
    }
    dim3 grid(N_TOT / BN, M_TOT / BM);   // (16, 256)
    gemm_kernel<<<grid, 256, SMEM_BYTES>>>(bias, out);
}